// round 8
// baseline (speedup 1.0000x reference)
#include <cuda_runtime.h>
#include <cstdint>

#define T_STEPS 1024
#define F_IN    64
#define HDIM    40
#define G4      160   // 4*H
#define R       4     // batch rows per recurrent block
#define NT2     480   // recurrent kernel: 5 A-warps + 10 B-warps

typedef unsigned long long ull;

// 512*1024*160 fp32 scratch for the precomputed input projection of LSTM A.
__device__ float g_xa[(size_t)512 * 1024 * 160];

// ---------------------------------------------------------------------------
// Packed f32x2 helpers
// ---------------------------------------------------------------------------
__device__ __forceinline__ ull pack2(float a, float b) {
    ull r; asm("mov.b64 %0, {%1,%2};" : "=l"(r) : "f"(a), "f"(b)); return r;
}
__device__ __forceinline__ void unpack2(ull v, float& a, float& b) {
    asm("mov.b64 {%0,%1}, %2;" : "=f"(a), "=f"(b) : "l"(v));
}
__device__ __forceinline__ void ffma2(ull& d, ull a, ull b) {
    asm("fma.rn.f32x2 %0, %1, %2, %0;" : "+l"(d) : "l"(a), "l"(b));
}

// ---------------------------------------------------------------------------
// MUFU activations
// ---------------------------------------------------------------------------
__device__ __forceinline__ float sigmoid_f(float x) {
    float e, r;
    asm("ex2.approx.f32 %0, %1;" : "=f"(e) : "f"(-1.4426950408889634f * x));
    asm("rcp.approx.f32 %0, %1;" : "=f"(r) : "f"(1.0f + e));
    return r;
}
__device__ __forceinline__ float tanh_f(float x) {
    float e, r;
    asm("ex2.approx.f32 %0, %1;" : "=f"(e) : "f"(2.8853900817779268f * x));
    asm("rcp.approx.f32 %0, %1;" : "=f"(r) : "f"(1.0f + e));
    return 1.0f - 2.0f * r;
}
// branchless gate activation: v = aa * 1/(1+2^(mm*z)) + bb
__device__ __forceinline__ float gate_act(float z, float mm, float aa, float bb) {
    float e, r;
    asm("ex2.approx.f32 %0, %1;" : "=f"(e) : "f"(mm * z));
    asm("rcp.approx.f32 %0, %1;" : "=f"(r) : "f"(1.0f + e));
    return fmaf(aa, r, bb);
}

__device__ __forceinline__ unsigned smem_u32(const void* p) {
    return (unsigned)__cvta_generic_to_shared(p);
}

// ===========================================================================
// Phase 1: xa[b][t][g] = seq[b,t,:] @ WaK[:,g] + ba[g]
// grid 512 (one block per batch row), 160 threads (thread = gate column g,
// WaK column in registers). cp.async ring over seq rows. High occupancy; the
// per-block barriers are hidden by other resident blocks.
// ===========================================================================
__global__ void __launch_bounds__(160)
xproj_kernel(const float* __restrict__ seq, const float* __restrict__ WaK,
             const float* __restrict__ ba)
{
    __shared__ __align__(16) float sx[8][F_IN];
    const int b = blockIdx.x;
    const int g = threadIdx.x;

    ull wk2[32];
    #pragma unroll
    for (int p = 0; p < 32; p++)
        wk2[p] = pack2(WaK[(2 * p) * G4 + g], WaK[(2 * p + 1) * G4 + g]);
    const float bias = ba[g];

    const float* sb = seq + (size_t)b * T_STEPS * F_IN;
    if (g < 16) {
        #pragma unroll
        for (int p = 0; p < 4; p++) {
            unsigned dst = smem_u32(&sx[p][g * 4]);
            asm volatile("cp.async.ca.shared.global [%0], [%1], 16;\n\t"
                         "cp.async.commit_group;\n" :: "r"(dst), "l"(sb + p * F_IN + g * 4));
        }
        asm volatile("cp.async.wait_group 2;");   // slots 0,1 done
    }
    __syncthreads();

    float* ocol = g_xa + (size_t)b * T_STEPS * G4 + g;
    for (int t = 0; t < T_STEPS; t++) {
        if (g < 16) {
            const int tf = t + 4;
            if (tf < T_STEPS) {
                unsigned dst = smem_u32(&sx[tf & 7][g * 4]);
                asm volatile("cp.async.ca.shared.global [%0], [%1], 16;"
                             :: "r"(dst), "l"(sb + (size_t)tf * F_IN + g * 4));
            }
            asm volatile("cp.async.commit_group;");
        }
        const ulonglong2* x2 = (const ulonglong2*)&sx[t & 7][0];
        ull a0 = 0ull, a1 = 0ull;
        #pragma unroll
        for (int p = 0; p < 16; p++) {
            ulonglong2 v = x2[p];
            ffma2(a0, wk2[2 * p],     v.x);
            ffma2(a1, wk2[2 * p + 1], v.y);
        }
        float x0, x1, x2f, x3;
        unpack2(a0, x0, x1); unpack2(a1, x2f, x3);
        ocol[(size_t)t * G4] = bias + ((x0 + x2f) + (x1 + x3));
        if (g < 16) asm volatile("cp.async.wait_group 2;");
        __syncthreads();
    }
}

// ===========================================================================
// Phase 2: recurrence. grid 128 (4 rows/block), 480 threads:
//   tid [0,160):   LSTM A, 5 warps, lane = q*8+u, j = w*8+u, g = q*40+j,
//                  each thread handles all 4 rows; only the 40-long h-dot on
//                  the critical path (xa streamed from g_xa via cp.async ring).
//   tid [160,480): LSTM B, 10 warps, row-pair rh = warp/5, 2 rows/thread,
//                  one step behind A. Ring loaders = tid [160,200).
// One barrier per step; gate exchange via shfl_xor 8/16/24; the q==0 lane of
// each unit owns c and writes h.
// ===========================================================================
struct __align__(16) Smem2 {
    float xa[8][R][G4];     // ring of xa rows: 8 * 2560 B = 20 KB
    float hA[R][HDIM];
    float hB[R][HDIM];
    float t1[R][10], yy[R][10], cc[R][20], dd[R][10];
};

__global__ void __launch_bounds__(NT2, 1)
recur_kernel(const float* __restrict__ feat,
             const float* __restrict__ WaR,
             const float* __restrict__ WbK,  const float* __restrict__ WbR, const float* __restrict__ bb,
             const float* __restrict__ Wg,   const float* __restrict__ bg,
             const float* __restrict__ Wh,   const float* __restrict__ bh,
             const float* __restrict__ Wc,   const float* __restrict__ bc,
             const float* __restrict__ Wd,   const float* __restrict__ bd,
             const float* __restrict__ Wo,   const float* __restrict__ bo,
             float* __restrict__ out)
{
    __shared__ Smem2 s;

    const int tid  = threadIdx.x;
    const int b4   = blockIdx.x * R;
    const bool isA = tid < 160;

    const int lane = tid & 31;
    const int q    = lane >> 3;        // gate: 0:i 1:f 2:g 3:o
    const int u    = lane & 7;
    const int wA = tid >> 5;                 // A warp 0..4
    const int wB = (tid - 160) >> 5;         // B warp 0..9
    const int jA = wA * 8 + u;
    const int jB = (wB % 5) * 8 + u;
    const int rh = wB / 5;                   // B row-pair
    const int j  = isA ? jA : jB;
    const int g  = q * HDIM + j;

    const bool isG = (q == 2);
    const float mm  = isG ? -2.8853900817779268f : -1.4426950408889634f;
    const float aa  = isG ? 2.0f : 1.0f;
    const float bbv = isG ? -1.0f : 0.0f;

    // ---- weights in registers (UNIONED across roles to cap reg count):
    //   A threads: w2[0..19]  = WaR column pairs
    //   B threads: w2[0..19]  = WbK column pairs, w2[20..39] = WbR pairs
    ull w2[40];
    float bias = 0.0f;
    if (isA) {
        #pragma unroll
        for (int p = 0; p < 20; p++)
            w2[p] = pack2(WaR[(2 * p) * G4 + g], WaR[(2 * p + 1) * G4 + g]);
    } else {
        #pragma unroll
        for (int p = 0; p < 20; p++)
            w2[p] = pack2(WbK[(2 * p) * G4 + g], WbK[(2 * p + 1) * G4 + g]);
        #pragma unroll
        for (int p = 0; p < 20; p++)
            w2[20 + p] = pack2(WbR[(2 * p) * G4 + g], WbR[(2 * p + 1) * G4 + g]);
        bias = bb[g];
    }

    float cA[R] = {0.f, 0.f, 0.f, 0.f};   // A q==0 lanes: c per row
    float cB[2] = {0.f, 0.f};             // B q==0 lanes: c per owned row

    if (tid < 160)                 ((float*)s.hA)[tid]        = 0.0f;
    else if (tid < 320)            ((float*)s.hB)[tid - 160]  = 0.0f;

    // ---- xa ring prologue: loaders tid [160,200), 64 B (4x16B) each ----
    const int ld = tid - 160;
    const int lr = (ld >= 0 && ld < 40) ? ld / 10 : 0;     // row 0..3
    const int lc = (ld >= 0 && ld < 40) ? (ld % 10) * 16 : 0;
    const bool isLd = (ld >= 0 && ld < 40);
    if (isLd) {
        #pragma unroll
        for (int p = 0; p < 4; p++) {
            const float* src = g_xa + ((size_t)(b4 + lr) * T_STEPS + p) * G4 + lc;
            #pragma unroll
            for (int c = 0; c < 4; c++) {
                unsigned dst = smem_u32(&s.xa[p][lr][lc + c * 4]);
                asm volatile("cp.async.ca.shared.global [%0], [%1], 16;"
                             :: "r"(dst), "l"(src + c * 4));
            }
            asm volatile("cp.async.commit_group;");
        }
        asm volatile("cp.async.wait_group 2;");   // slots 0,1 ready
    }
    __syncthreads();

    // ---- main recurrence: one barrier per step ----
    for (int t = 0; t <= T_STEPS; t++) {
        if (isLd) {                        // prefetch slot t+4
            const int tf = t + 4;
            if (tf < T_STEPS) {
                const float* src = g_xa + ((size_t)(b4 + lr) * T_STEPS + tf) * G4 + lc;
                #pragma unroll
                for (int c = 0; c < 4; c++) {
                    unsigned dst = smem_u32(&s.xa[tf & 7][lr][lc + c * 4]);
                    asm volatile("cp.async.ca.shared.global [%0], [%1], 16;"
                                 :: "r"(dst), "l"(src + c * 4));
                }
            }
            asm volatile("cp.async.commit_group;");
        }

        if (isA) {
            if (t < T_STEPS) {
                float v[R];
                #pragma unroll
                for (int r = 0; r < R; r++) {
                    const ulonglong2* h2 = (const ulonglong2*)&s.hA[r][0];
                    ull a0 = 0ull, a1 = 0ull;
                    #pragma unroll
                    for (int p = 0; p < 10; p++) {
                        ulonglong2 hv = h2[p];
                        ffma2(a0, w2[2 * p],     hv.x);
                        ffma2(a1, w2[2 * p + 1], hv.y);
                    }
                    float x0, x1, x2f, x3;
                    unpack2(a0, x0, x1); unpack2(a1, x2f, x3);
                    float z = s.xa[t & 7][r][g] + ((x0 + x2f) + (x1 + x3));
                    v[r] = gate_act(z, mm, aa, bbv);
                }
                #pragma unroll
                for (int r = 0; r < R; r++) {
                    float fv = __shfl_xor_sync(0xffffffffu, v[r], 8);
                    float gv = __shfl_xor_sync(0xffffffffu, v[r], 16);
                    float ov = __shfl_xor_sync(0xffffffffu, v[r], 24);
                    if (q == 0) {
                        cA[r] = fmaf(fv, cA[r], v[r] * gv);
                        s.hA[r][j] = ov * tanh_f(cA[r]);
                    }
                }
            }
        } else {
            if (t >= 1) {
                float v[2];
                #pragma unroll
                for (int k = 0; k < 2; k++) {
                    const int r = 2 * rh + k;
                    const ulonglong2* xa2 = (const ulonglong2*)&s.hA[r][0];  // input
                    const ulonglong2* hb2 = (const ulonglong2*)&s.hB[r][0];  // recurrent
                    ull a0 = 0ull, a1 = 0ull;
                    #pragma unroll
                    for (int p = 0; p < 10; p++) {
                        ulonglong2 xv = xa2[p];
                        ulonglong2 hv = hb2[p];
                        ffma2(a0, w2[2 * p],          xv.x);
                        ffma2(a1, w2[2 * p + 1],      xv.y);
                        ffma2(a0, w2[20 + 2 * p],     hv.x);
                        ffma2(a1, w2[20 + 2 * p + 1], hv.y);
                    }
                    float x0, x1, x2f, x3;
                    unpack2(a0, x0, x1); unpack2(a1, x2f, x3);
                    float z = bias + ((x0 + x2f) + (x1 + x3));
                    v[k] = gate_act(z, mm, aa, bbv);
                }
                #pragma unroll
                for (int k = 0; k < 2; k++) {
                    const int r = 2 * rh + k;
                    float fv = __shfl_xor_sync(0xffffffffu, v[k], 8);
                    float gv = __shfl_xor_sync(0xffffffffu, v[k], 16);
                    float ov = __shfl_xor_sync(0xffffffffu, v[k], 24);
                    if (q == 0) {
                        cB[k] = fmaf(fv, cB[k], v[k] * gv);
                        s.hB[r][j] = ov * tanh_f(cB[k]);
                    }
                }
            }
            if (isLd)
                asm volatile("cp.async.wait_group 2;");   // slots <= t+2 done
        }
        __syncthreads();
    }

    // ---- dense tail on threads [0,160): r = tid/40, u' = tid%40 ----
    {
        const int r  = tid / HDIM;
        const int uu = tid % HDIM;
        const bool act = tid < 160;
        const float* fb = feat + (size_t)(b4 + r) * F_IN;
        if (act && uu < 10) {
            float a = bg[uu];
            #pragma unroll 8
            for (int k = 0; k < F_IN; k++) a = fmaf(fb[k], Wg[k * 10 + uu], a);
            s.t1[r][uu] = tanh_f(a);
        }
        __syncthreads();
        if (act && uu < 10) {
            float a = bh[uu];
            #pragma unroll
            for (int k = 0; k < 10; k++) a = fmaf(s.t1[r][k], Wh[k * 10 + uu], a);
            s.yy[r][uu] = tanh_f(a);
        }
        __syncthreads();
        if (act && uu < 20) {
            float a = bc[uu];
            #pragma unroll
            for (int k = 0; k < HDIM; k++) a = fmaf(s.hB[r][k], Wc[k * 20 + uu], a);
            #pragma unroll
            for (int k = 0; k < 10; k++)   a = fmaf(s.yy[r][k], Wc[(HDIM + k) * 20 + uu], a);
            s.cc[r][uu] = fmaxf(a, 0.0f);
        }
        __syncthreads();
        if (act && uu < 10) {
            float a = bd[uu];
            #pragma unroll
            for (int k = 0; k < 20; k++) a = fmaf(s.cc[r][k], Wd[k * 10 + uu], a);
            s.dd[r][uu] = fmaxf(a, 0.0f);
        }
        __syncthreads();
        if (act && uu == 0) {
            float a = bo[0];
            #pragma unroll
            for (int k = 0; k < 10; k++) a = fmaf(s.dd[r][k], Wo[k], a);
            out[b4 + r] = sigmoid_f(a);
        }
    }
}

// ---------------------------------------------------------------------------
extern "C" void kernel_launch(void* const* d_in, const int* in_sizes, int n_in,
                              void* d_out, int out_size)
{
    (void)in_sizes; (void)n_in; (void)out_size;
    const float* seq  = (const float*)d_in[0];
    const float* feat = (const float*)d_in[1];
    const float* WaK  = (const float*)d_in[2];
    const float* WaR  = (const float*)d_in[3];
    const float* ba   = (const float*)d_in[4];
    const float* WbK  = (const float*)d_in[5];
    const float* WbR  = (const float*)d_in[6];
    const float* bb   = (const float*)d_in[7];
    const float* Wg   = (const float*)d_in[8];
    const float* bg   = (const float*)d_in[9];
    const float* Wh   = (const float*)d_in[10];
    const float* bh   = (const float*)d_in[11];
    const float* Wc   = (const float*)d_in[12];
    const float* bc   = (const float*)d_in[13];
    const float* Wd   = (const float*)d_in[14];
    const float* bd   = (const float*)d_in[15];
    const float* Wo   = (const float*)d_in[16];
    const float* bo   = (const float*)d_in[17];
    float* out = (float*)d_out;

    xproj_kernel<<<512, 160>>>(seq, WaK, ba);
    recur_kernel<<<512 / R, NT2>>>(feat, WaR, WbK, WbR, bb,
                                   Wg, bg, Wh, bh, Wc, bc, Wd, bd, Wo, bo, out);
}